// round 4
// baseline (speedup 1.0000x reference)
#include <cuda_runtime.h>
#include <cstdint>
#include <math.h>

#define TOK   8192
#define DIM   1024
#define HID   2048
#define NE    8
#define CAP   1280
#define MAXPE 2560   // 2*CAP, max entries per expert

#define BM 128
#define BN 64
#define BK 16
#define LDS_PAD 20   // row stride in words for smem tiles (conflict-free for frag reads)

// ---------------- scratch (device globals; no allocation) ----------------
__device__ int   g_cnt[NE];
__device__ int   g_topi[TOK * 2];
__device__ float g_topw[TOK * 2];
__device__ int   g_list[NE * MAXPE];
__device__ int   g_slot[TOK * 2];          // -1 = dropped, else e*MAXPE+pos
__device__ float g_act[(size_t)NE * MAXPE * HID];  // ~168 MB
__device__ float g_y [(size_t)NE * MAXPE * DIM];   // ~84 MB

// ---------------- helpers ----------------
__device__ __forceinline__ uint32_t f2tf(float x) {
    uint32_t r;
    asm("cvt.rna.tf32.f32 %0, %1;" : "=r"(r) : "f"(x));
    return r;
}

__device__ __forceinline__ void mma8(float c[4], const uint32_t a[4], const uint32_t b[2]) {
    asm volatile(
        "mma.sync.aligned.m16n8k8.row.col.f32.tf32.tf32.f32 "
        "{%0,%1,%2,%3},{%4,%5,%6,%7},{%8,%9},{%0,%1,%2,%3};"
        : "+f"(c[0]), "+f"(c[1]), "+f"(c[2]), "+f"(c[3])
        : "r"(a[0]), "r"(a[1]), "r"(a[2]), "r"(a[3]), "r"(b[0]), "r"(b[1]));
}

__device__ __forceinline__ float silu_f(float g) {
    return g / (1.0f + expf(-g));
}

// ---------------- 0: zero counters ----------------
__global__ void zero_cnt_kernel() {
    if (threadIdx.x < NE) g_cnt[threadIdx.x] = 0;
}

// ---------------- 1: router ----------------
// One warp per token. gate_w (8x1024 fp32 = 32KB) staged in smem.
__global__ void router_kernel(const float* __restrict__ x, const float* __restrict__ gw) {
    __shared__ float4 sgw[NE * 256];
    int tid = threadIdx.x;
    for (int i = tid; i < NE * 256; i += 256) sgw[i] = ((const float4*)gw)[i];
    __syncthreads();

    int lane = tid & 31, w = tid >> 5;
    int t = blockIdx.x * 8 + w;
    const float4* xr = (const float4*)(x + (size_t)t * DIM);

    float acc[NE];
#pragma unroll
    for (int e = 0; e < NE; e++) acc[e] = 0.0f;

    for (int i = lane; i < DIM / 4; i += 32) {
        float4 xv = xr[i];
#pragma unroll
        for (int e = 0; e < NE; e++) {
            float4 g = sgw[e * 256 + i];
            acc[e] += xv.x * g.x + xv.y * g.y + xv.z * g.z + xv.w * g.w;
        }
    }
#pragma unroll
    for (int off = 16; off; off >>= 1)
#pragma unroll
        for (int e = 0; e < NE; e++) acc[e] += __shfl_down_sync(0xffffffffu, acc[e], off);

    if (lane == 0) {
        float mx = acc[0];
#pragma unroll
        for (int e = 1; e < NE; e++) mx = fmaxf(mx, acc[e]);
        float ex[NE], Z = 0.0f;
#pragma unroll
        for (int e = 0; e < NE; e++) { ex[e] = expf(acc[e] - mx); Z += ex[e]; }

        int i1 = 0; float p1 = ex[0];
#pragma unroll
        for (int e = 1; e < NE; e++) if (ex[e] > p1) { p1 = ex[e]; i1 = e; }
        int i2 = -1; float p2 = -1.0f;
#pragma unroll
        for (int e = 0; e < NE; e++) if (e != i1 && ex[e] > p2) { p2 = ex[e]; i2 = e; }

        p1 /= Z; p2 /= Z;
        float s = p1 + p2 + 1e-9f;
        g_topi[t * 2 + 0] = i1;
        g_topi[t * 2 + 1] = i2;
        g_topw[t * 2 + 0] = p1 / s;
        g_topw[t * 2 + 1] = p2 / s;
    }
}

// ---------------- 2: exact token-order capacity scan ----------------
// 16 blocks: block b handles (k = b>>3, e = b&7). Sequential chunk scan over T
// reproduces the reference's cumsum rank exactly. Storage position comes from
// an atomic counter (order within list is irrelevant to the math).
__global__ void scan_kernel() {
    int b = blockIdx.x;
    int k = b >> 3, e = b & 7;
    __shared__ int warp_tot[8];
    __shared__ int warp_off[8];
    __shared__ int blk_tot;
    int tid = threadIdx.x, lane = tid & 31, w = tid >> 5;
    int base = 0;

    for (int c0 = 0; c0 < TOK; c0 += 256) {
        int t = c0 + tid;
        bool flag = (g_topi[t * 2 + k] == e);
        unsigned m = __ballot_sync(0xffffffffu, flag);
        int pre = __popc(m & ((1u << lane) - 1u));
        if (lane == 0) warp_tot[w] = __popc(m);
        __syncthreads();
        if (tid == 0) {
            int s = 0;
#pragma unroll
            for (int i = 0; i < 8; i++) { warp_off[i] = s; s += warp_tot[i]; }
            blk_tot = s;
        }
        __syncthreads();
        if (flag) {
            int rank = base + warp_off[w] + pre;
            if (rank < CAP) {
                int pos = atomicAdd(&g_cnt[e], 1);
                g_list[e * MAXPE + pos] = t;
                g_slot[t * 2 + k] = e * MAXPE + pos;
            } else {
                g_slot[t * 2 + k] = -1;
            }
        }
        base += blk_tot;
        __syncthreads();
    }
}

// ---------------- 3: fused gate+up GEMM (TF32 mma), epilogue silu(g)*u ----------------
// C[m][n] = sum_k A[m][k] * W[n][k]; A rows gathered from x via g_list.
// grid (MAXPE/BM, HID/BN, NE), block 256 (8 warps = 4M x 2N), warp tile 32x32.
__global__ __launch_bounds__(256) void gemm_gateup_kernel(
    const float* __restrict__ x,
    const float* __restrict__ Wg,
    const float* __restrict__ Wu)
{
    int e = blockIdx.z;
    int cnt = g_cnt[e];
    int m0 = blockIdx.x * BM;
    if (m0 >= cnt) return;
    int n0 = blockIdx.y * BN;

    __shared__ uint32_t As[BM * LDS_PAD];
    __shared__ uint32_t Bgs[BN * LDS_PAD];
    __shared__ uint32_t Bus[BN * LDS_PAD];

    int tid = threadIdx.x, lane = tid & 31, w = tid >> 5;
    int wm = w >> 1, wn = w & 1;

    float accG[2][4][4], accU[2][4][4];
#pragma unroll
    for (int i = 0; i < 2; i++)
#pragma unroll
        for (int j = 0; j < 4; j++)
#pragma unroll
            for (int r = 0; r < 4; r++) { accG[i][j][r] = 0.0f; accU[i][j][r] = 0.0f; }

    const float* Wge = Wg + (size_t)e * HID * DIM;
    const float* Wue = Wu + (size_t)e * HID * DIM;

    // pre-resolve the two A rows this thread loads
    int arow[2], atok[2];
#pragma unroll
    for (int j = 0; j < 2; j++) {
        int idx = tid + j * 256;
        arow[j] = idx >> 2;
        int mrow = m0 + arow[j];
        atok[j] = (mrow < cnt) ? g_list[e * MAXPE + mrow] : -1;
    }
    int ac4 = tid & 3;
    int brow = tid >> 2, bc4 = tid & 3;

    for (int k0 = 0; k0 < DIM; k0 += BK) {
        // load A (gathered)
#pragma unroll
        for (int j = 0; j < 2; j++) {
            float4 v = make_float4(0.f, 0.f, 0.f, 0.f);
            if (atok[j] >= 0)
                v = *(const float4*)(x + (size_t)atok[j] * DIM + k0 + ac4 * 4);
            uint32_t* dst = &As[arow[j] * LDS_PAD + ac4 * 4];
            dst[0] = f2tf(v.x); dst[1] = f2tf(v.y); dst[2] = f2tf(v.z); dst[3] = f2tf(v.w);
        }
        // load B (gate + up)
        {
            float4 vg = *(const float4*)(Wge + (size_t)(n0 + brow) * DIM + k0 + bc4 * 4);
            float4 vu = *(const float4*)(Wue + (size_t)(n0 + brow) * DIM + k0 + bc4 * 4);
            uint32_t* dg = &Bgs[brow * LDS_PAD + bc4 * 4];
            uint32_t* du = &Bus[brow * LDS_PAD + bc4 * 4];
            dg[0] = f2tf(vg.x); dg[1] = f2tf(vg.y); dg[2] = f2tf(vg.z); dg[3] = f2tf(vg.w);
            du[0] = f2tf(vu.x); du[1] = f2tf(vu.y); du[2] = f2tf(vu.z); du[3] = f2tf(vu.w);
        }
        __syncthreads();

#pragma unroll
        for (int ks = 0; ks < 2; ks++) {
            uint32_t a[2][4];
#pragma unroll
            for (int mt = 0; mt < 2; mt++) {
                int r0 = wm * 32 + mt * 16 + (lane >> 2);
                int c0 = ks * 8 + (lane & 3);
                a[mt][0] = As[r0 * LDS_PAD + c0];
                a[mt][1] = As[(r0 + 8) * LDS_PAD + c0];
                a[mt][2] = As[r0 * LDS_PAD + c0 + 4];
                a[mt][3] = As[(r0 + 8) * LDS_PAD + c0 + 4];
            }
            uint32_t bg[4][2], bu[4][2];
#pragma unroll
            for (int nt = 0; nt < 4; nt++) {
                int n = wn * 32 + nt * 8 + (lane >> 2);
                int kc = ks * 8 + (lane & 3);
                bg[nt][0] = Bgs[n * LDS_PAD + kc];
                bg[nt][1] = Bgs[n * LDS_PAD + kc + 4];
                bu[nt][0] = Bus[n * LDS_PAD + kc];
                bu[nt][1] = Bus[n * LDS_PAD + kc + 4];
            }
#pragma unroll
            for (int mt = 0; mt < 2; mt++)
#pragma unroll
                for (int nt = 0; nt < 4; nt++) {
                    mma8(accG[mt][nt], a[mt], bg[nt]);
                    mma8(accU[mt][nt], a[mt], bu[nt]);
                }
        }
        __syncthreads();
    }

    // epilogue: act = silu(g) * u
    float* actb = g_act + (size_t)e * MAXPE * HID;
#pragma unroll
    for (int mt = 0; mt < 2; mt++)
#pragma unroll
        for (int nt = 0; nt < 4; nt++) {
            int rbase = m0 + wm * 32 + mt * 16 + (lane >> 2);
            int cbase = n0 + wn * 32 + nt * 8 + 2 * (lane & 3);
#pragma unroll
            for (int h = 0; h < 2; h++) {
                int r = rbase + 8 * h;
                if (r < cnt) {
                    float g0 = accG[mt][nt][2 * h], g1 = accG[mt][nt][2 * h + 1];
                    float u0 = accU[mt][nt][2 * h], u1 = accU[mt][nt][2 * h + 1];
                    actb[(size_t)r * HID + cbase]     = silu_f(g0) * u0;
                    actb[(size_t)r * HID + cbase + 1] = silu_f(g1) * u1;
                }
            }
        }
}

// ---------------- 4: down GEMM (TF32 mma) ----------------
// y[m][n] = sum_k act[m][k] * Wd[n][k], K = HID, N = DIM.
__global__ __launch_bounds__(256) void gemm_down_kernel(const float* __restrict__ Wd)
{
    int e = blockIdx.z;
    int cnt = g_cnt[e];
    int m0 = blockIdx.x * BM;
    if (m0 >= cnt) return;
    int n0 = blockIdx.y * BN;

    __shared__ uint32_t As[BM * LDS_PAD];
    __shared__ uint32_t Bs[BN * LDS_PAD];

    int tid = threadIdx.x, lane = tid & 31, w = tid >> 5;
    int wm = w >> 1, wn = w & 1;

    float acc[2][4][4];
#pragma unroll
    for (int i = 0; i < 2; i++)
#pragma unroll
        for (int j = 0; j < 4; j++)
#pragma unroll
            for (int r = 0; r < 4; r++) acc[i][j][r] = 0.0f;

    const float* Aact = g_act + (size_t)e * MAXPE * HID;
    const float* Wde  = Wd + (size_t)e * DIM * HID;

    int ac4 = tid & 3;
    int arow0 = tid >> 2;
    int brow = tid >> 2, bc4 = tid & 3;

    for (int k0 = 0; k0 < HID; k0 += BK) {
#pragma unroll
        for (int j = 0; j < 2; j++) {
            int r = arow0 + j * 64;
            float4 v = *(const float4*)(Aact + (size_t)(m0 + r) * HID + k0 + ac4 * 4);
            uint32_t* dst = &As[r * LDS_PAD + ac4 * 4];
            dst[0] = f2tf(v.x); dst[1] = f2tf(v.y); dst[2] = f2tf(v.z); dst[3] = f2tf(v.w);
        }
        {
            float4 v = *(const float4*)(Wde + (size_t)(n0 + brow) * HID + k0 + bc4 * 4);
            uint32_t* dst = &Bs[brow * LDS_PAD + bc4 * 4];
            dst[0] = f2tf(v.x); dst[1] = f2tf(v.y); dst[2] = f2tf(v.z); dst[3] = f2tf(v.w);
        }
        __syncthreads();

#pragma unroll
        for (int ks = 0; ks < 2; ks++) {
            uint32_t a[2][4];
#pragma unroll
            for (int mt = 0; mt < 2; mt++) {
                int r0 = wm * 32 + mt * 16 + (lane >> 2);
                int c0 = ks * 8 + (lane & 3);
                a[mt][0] = As[r0 * LDS_PAD + c0];
                a[mt][1] = As[(r0 + 8) * LDS_PAD + c0];
                a[mt][2] = As[r0 * LDS_PAD + c0 + 4];
                a[mt][3] = As[(r0 + 8) * LDS_PAD + c0 + 4];
            }
            uint32_t b[4][2];
#pragma unroll
            for (int nt = 0; nt < 4; nt++) {
                int n = wn * 32 + nt * 8 + (lane >> 2);
                int kc = ks * 8 + (lane & 3);
                b[nt][0] = Bs[n * LDS_PAD + kc];
                b[nt][1] = Bs[n * LDS_PAD + kc + 4];
            }
#pragma unroll
            for (int mt = 0; mt < 2; mt++)
#pragma unroll
                for (int nt = 0; nt < 4; nt++)
                    mma8(acc[mt][nt], a[mt], b[nt]);
        }
        __syncthreads();
    }

    float* yb = g_y + (size_t)e * MAXPE * DIM;
#pragma unroll
    for (int mt = 0; mt < 2; mt++)
#pragma unroll
        for (int nt = 0; nt < 4; nt++) {
            int rbase = m0 + wm * 32 + mt * 16 + (lane >> 2);
            int cbase = n0 + wn * 32 + nt * 8 + 2 * (lane & 3);
#pragma unroll
            for (int h = 0; h < 2; h++) {
                int r = rbase + 8 * h;
                if (r < cnt) {
                    yb[(size_t)r * DIM + cbase]     = acc[mt][nt][2 * h];
                    yb[(size_t)r * DIM + cbase + 1] = acc[mt][nt][2 * h + 1];
                }
            }
        }
}

// ---------------- 5: combine ----------------
// out[t] = w0 * y[slot0] + w1 * y[slot1] (0 contributions when dropped).
__global__ void combine_kernel(float* __restrict__ out) {
    int t = blockIdx.x;
    int tid = threadIdx.x;
    int s0 = g_slot[t * 2 + 0];
    int s1 = g_slot[t * 2 + 1];
    float w0 = g_topw[t * 2 + 0];
    float w1 = g_topw[t * 2 + 1];

    const float4* y4 = (const float4*)g_y;
    float4 r = make_float4(0.f, 0.f, 0.f, 0.f);
    int c4 = tid;  // 256 threads * 4 floats = 1024 = DIM
    if (s0 >= 0) {
        float4 v = y4[(size_t)s0 * (DIM / 4) + c4];
        r.x += w0 * v.x; r.y += w0 * v.y; r.z += w0 * v.z; r.w += w0 * v.w;
    }
    if (s1 >= 0) {
        float4 v = y4[(size_t)s1 * (DIM / 4) + c4];
        r.x += w1 * v.x; r.y += w1 * v.y; r.z += w1 * v.z; r.w += w1 * v.w;
    }
    ((float4*)out)[(size_t)t * (DIM / 4) + c4] = r;
}

// ---------------- launch ----------------
extern "C" void kernel_launch(void* const* d_in, const int* in_sizes, int n_in,
                              void* d_out, int out_size) {
    const float* x  = (const float*)d_in[0];
    const float* gw = (const float*)d_in[1];
    const float* wg = (const float*)d_in[2];
    const float* wu = (const float*)d_in[3];
    const float* wd = (const float*)d_in[4];
    float* out = (float*)d_out;

    zero_cnt_kernel<<<1, 32>>>();
    router_kernel<<<TOK / 8, 256>>>(x, gw);
    scan_kernel<<<16, 256>>>();
    gemm_gateup_kernel<<<dim3(MAXPE / BM, HID / BN, NE), 256>>>(x, wg, wu);
    gemm_down_kernel<<<dim3(MAXPE / BM, DIM / BN, NE), 256>>>(wd);
    combine_kernel<<<TOK, 256>>>(out);
}